// round 3
// baseline (speedup 1.0000x reference)
#include <cuda_runtime.h>
#include <cuda_bf16.h>

// ChannelPruner: out[b,o,h,w] = sum_c w[o,c] * x[b,c,h,w]
// x: (32, 256, 56, 56) fp32, w: (256,256,1,1) fp32 (sparse rows, discovered at
// runtime -> correct for ANY w).
//
// R3: single-wave grid (1024 blocks = 256 o x 4 batch-groups), one weight-row
// compaction per block amortized over 8 planes; MLP-4 load bursts back-to-back
// so loads stay outstanding ~90% of block lifetime; streaming stores (__stcs)
// keep x L2-resident across graph replays.

#define N_CH    256
#define BATCH   32
#define HW4     784                   // (56*56)/4 float4 per plane
#define PLANE4  HW4
#define BSTRIDE (N_CH * HW4)          // float4 per batch (200704)
#define BG      8                     // batches per block
#define NGRP    (BATCH / BG)          // 4
#define NBLK    (N_CH * NGRP)         // 1024 blocks -> single wave

__global__ __launch_bounds__(256, 8) void prune_fused(const float4* __restrict__ x,
                                                      const float*  __restrict__ w,
                                                      float4* __restrict__ out) {
    __shared__ int   s_cols[N_CH];
    __shared__ float s_vals[N_CH];
    __shared__ int   s_warp_off[9];

    const int tid  = threadIdx.x;
    const int lane = tid & 31;
    const int wid  = tid >> 5;

    const int o  = blockIdx.x & (N_CH - 1);
    const int b0 = (blockIdx.x >> 8) * BG;

    // ---- prologue: deterministic compaction of w row o (once per 8 planes) ----
    const float wv = __ldg(&w[o * N_CH + tid]);
    const unsigned mask = __ballot_sync(0xffffffffu, wv != 0.0f);
    if (lane == 0) s_warp_off[wid + 1] = __popc(mask);
    __syncthreads();
    if (tid == 0) {
        int acc = 0;
        s_warp_off[0] = 0;
#pragma unroll
        for (int i = 0; i < 8; i++) { acc += s_warp_off[i + 1]; s_warp_off[i + 1] = acc; }
    }
    __syncthreads();
    if (wv != 0.0f) {
        const int pos = s_warp_off[wid] + __popc(mask & ((1u << lane) - 1u));
        s_cols[pos] = tid;
        s_vals[pos] = wv;
    }
    __syncthreads();
    const int nnz = s_warp_off[8];

    const bool has3 = tid < (HW4 - 768);   // tid < 16

    // ---- body: 8 planes, each 4 float4/thread with 4 independent loads ----
    for (int bi = 0; bi < BG; bi++) {
        const size_t bbase = (size_t)(b0 + bi) * BSTRIDE;
        const float4* xb = x + bbase;

        float4 a0 = make_float4(0.f, 0.f, 0.f, 0.f);
        float4 a1 = a0, a2 = a0, a3 = a0;

        for (int j = 0; j < nnz; j++) {
            const int   c = s_cols[j];
            const float v = s_vals[j];
            const float4* xc = xb + (size_t)c * PLANE4 + tid;
            const float4 r0 = __ldg(xc);
            const float4 r1 = __ldg(xc + 256);
            const float4 r2 = __ldg(xc + 512);
            float4 r3 = make_float4(0.f, 0.f, 0.f, 0.f);
            if (has3) r3 = __ldg(xc + 768);

            a0.x += v * r0.x; a0.y += v * r0.y; a0.z += v * r0.z; a0.w += v * r0.w;
            a1.x += v * r1.x; a1.y += v * r1.y; a1.z += v * r1.z; a1.w += v * r1.w;
            a2.x += v * r2.x; a2.y += v * r2.y; a2.z += v * r2.z; a2.w += v * r2.w;
            a3.x += v * r3.x; a3.y += v * r3.y; a3.z += v * r3.z; a3.w += v * r3.w;
        }

        float4* ob = out + bbase + (size_t)o * PLANE4 + tid;
        __stcs(ob,       a0);
        __stcs(ob + 256, a1);
        __stcs(ob + 512, a2);
        if (has3) __stcs(ob + 768, a3);
    }
}

extern "C" void kernel_launch(void* const* d_in, const int* in_sizes, int n_in,
                              void* d_out, int out_size) {
    const float4* x = (const float4*)d_in[0];
    const float*  w = (const float*)d_in[1];
    float4* out = (float4*)d_out;

    prune_fused<<<NBLK, 256>>>(x, w, out);
}

// round 4
// speedup vs baseline: 1.0626x; 1.0626x over previous
#include <cuda_runtime.h>
#include <cuda_bf16.h>

// ChannelPruner: out[b,o,h,w] = sum_c w[o,c] * x[b,c,h,w]
// x: (32, 256, 56, 56) fp32; w: (256,256,1,1) fp32, sparse rows discovered at
// runtime (correct for ANY w).
//
// R4: grid = 256 o x 16 batch-groups = 4096 blocks (BG=2 planes per block).
// Warp-0-only ballot compaction of the w row (single __syncthreads), then the
// body issues 8 independent LDG.128 per nonzero channel (2 batches x 3 offsets
// + tail) before any FMA -> high MLP, minimal prologue dead time.

#define N_CH    256
#define BATCH   32
#define HW4     784                   // (56*56)/4 float4 per plane
#define BSTRIDE (N_CH * HW4)          // float4 per batch
#define BG      2
#define NBLK    (N_CH * (BATCH / BG)) // 4096

__global__ __launch_bounds__(256) void prune_fused(const float4* __restrict__ x,
                                                   const float*  __restrict__ w,
                                                   float4* __restrict__ out) {
    __shared__ int   s_cols[N_CH];
    __shared__ float s_vals[N_CH];
    __shared__ int   s_nnz;

    const int tid  = threadIdx.x;
    const int lane = tid & 31;
    const int wid  = tid >> 5;

    const int o  = blockIdx.x & (N_CH - 1);
    const int b0 = (blockIdx.x >> 8) * BG;

    // ---- prologue: warp 0 compacts w row o (deterministic order) ----
    if (wid == 0) {
        const float4* wr4 = (const float4*)(w + o * N_CH);
        const float4 w0 = __ldg(wr4 + lane * 2);
        const float4 w1 = __ldg(wr4 + lane * 2 + 1);
        float v[8] = {w0.x, w0.y, w0.z, w0.w, w1.x, w1.y, w1.z, w1.w};

        int cnt = 0;
#pragma unroll
        for (int k = 0; k < 8; k++) if (v[k] != 0.0f) cnt++;

        int scan = cnt;                       // inclusive scan over lanes
#pragma unroll
        for (int d = 1; d < 32; d <<= 1) {
            int t = __shfl_up_sync(0xffffffffu, scan, d);
            if (lane >= d) scan += t;
        }
        int p = scan - cnt;                   // exclusive offset
        const int base = lane * 8;
#pragma unroll
        for (int k = 0; k < 8; k++) {
            if (v[k] != 0.0f) { s_cols[p] = base + k; s_vals[p] = v[k]; p++; }
        }
        if (lane == 31) s_nnz = scan;
    }
    __syncthreads();

    const int  nnz  = s_nnz;
    const bool tail = tid < (HW4 - 768);      // tid < 16

    const size_t pb0 = (size_t)b0 * BSTRIDE;
    const size_t pb1 = pb0 + BSTRIDE;

    float4 z = make_float4(0.f, 0.f, 0.f, 0.f);
    float4 a00 = z, a01 = z, a02 = z, a03 = z;   // batch b0
    float4 a10 = z, a11 = z, a12 = z, a13 = z;   // batch b0+1

    for (int j = 0; j < nnz; j++) {
        const int    c = s_cols[j];
        const float  v = s_vals[j];
        const size_t coff = (size_t)c * HW4 + tid;
        const float4* x0 = x + pb0 + coff;
        const float4* x1 = x + pb1 + coff;

        // 8 independent loads issued before any FMA
        const float4 r00 = __ldg(x0);
        const float4 r01 = __ldg(x0 + 256);
        const float4 r02 = __ldg(x0 + 512);
        const float4 r10 = __ldg(x1);
        const float4 r11 = __ldg(x1 + 256);
        const float4 r12 = __ldg(x1 + 512);
        float4 r03 = z, r13 = z;
        if (tail) { r03 = __ldg(x0 + 768); r13 = __ldg(x1 + 768); }

        a00.x += v * r00.x; a00.y += v * r00.y; a00.z += v * r00.z; a00.w += v * r00.w;
        a01.x += v * r01.x; a01.y += v * r01.y; a01.z += v * r01.z; a01.w += v * r01.w;
        a02.x += v * r02.x; a02.y += v * r02.y; a02.z += v * r02.z; a02.w += v * r02.w;
        a10.x += v * r10.x; a10.y += v * r10.y; a10.z += v * r10.z; a10.w += v * r10.w;
        a11.x += v * r11.x; a11.y += v * r11.y; a11.z += v * r11.z; a11.w += v * r11.w;
        a12.x += v * r12.x; a12.y += v * r12.y; a12.z += v * r12.z; a12.w += v * r12.w;
        if (tail) {
            a03.x += v * r03.x; a03.y += v * r03.y; a03.z += v * r03.z; a03.w += v * r03.w;
            a13.x += v * r13.x; a13.y += v * r13.y; a13.z += v * r13.z; a13.w += v * r13.w;
        }
    }

    const size_t ooff = (size_t)o * HW4 + tid;
    float4* o0 = out + pb0 + ooff;
    float4* o1 = out + pb1 + ooff;
    __stcs(o0,       a00);
    __stcs(o0 + 256, a01);
    __stcs(o0 + 512, a02);
    __stcs(o1,       a10);
    __stcs(o1 + 256, a11);
    __stcs(o1 + 512, a12);
    if (tail) { __stcs(o0 + 768, a03); __stcs(o1 + 768, a13); }
}

extern "C" void kernel_launch(void* const* d_in, const int* in_sizes, int n_in,
                              void* d_out, int out_size) {
    const float4* x = (const float4*)d_in[0];
    const float*  w = (const float*)d_in[1];
    float4* out = (float4*)d_out;

    prune_fused<<<NBLK, 256>>>(x, w, out);
}